// round 4
// baseline (speedup 1.0000x reference)
#include <cuda_runtime.h>
#include <cuda_bf16.h>
#include <cstdint>

// Problem constants (fixed by the reference)
#define BB 256
#define TT 4096
#define FF 16
#define HH 64
#define NROWS (256*4096)   // 1048576 rows of (b,t)

// -------------------- scratch (device globals; no allocs allowed) -----------
__device__ float g_xi [(size_t)NROWS * 192];  // xi1, then reused as xi2 (805 MB)
__device__ float g_aux[(size_t)NROWS * 64];   // xp, then reused as o2   (268 MB)
__device__ float g_o1 [(size_t)NROWS * 64];   // o1adj                   (268 MB)

// -------------------- packed f32x2 helpers ----------------------------------
__device__ __forceinline__ unsigned long long pk2(float lo, float hi) {
    unsigned long long d;
    asm("mov.b64 %0, {%1, %2};" : "=l"(d) : "f"(lo), "f"(hi));
    return d;
}
__device__ __forceinline__ void unpk2(unsigned long long v, float& lo, float& hi) {
    asm("mov.b64 {%0, %1}, %2;" : "=f"(lo), "=f"(hi) : "l"(v));
}
__device__ __forceinline__ unsigned long long ffma2(unsigned long long a,
                                                    unsigned long long b,
                                                    unsigned long long c) {
    unsigned long long d;
    asm("fma.rn.f32x2 %0, %1, %2, %3;" : "=l"(d) : "l"(a), "l"(b), "l"(c));
    return d;
}
__device__ __forceinline__ unsigned long long fadd2(unsigned long long a,
                                                    unsigned long long b) {
    unsigned long long d;
    asm("add.rn.f32x2 %0, %1, %2;" : "=l"(d) : "l"(a), "l"(b));
    return d;
}

__device__ __forceinline__ float sigmf(float x) {
    return __fdividef(1.0f, 1.0f + __expf(-x));
}
__device__ __forceinline__ float tanh_f(float x) {
    return __fdividef(2.0f, 1.0f + __expf(-2.0f * x)) - 1.0f;
}

// ============================================================================
// proj1: for each (b,t) row: xi1 = x@Wi1 + bi1 (192), xp = x@Wp + bp (64)
// Block 256 = 2 row-groups x 128 output-pairs. Weights (K=16) in registers as
// f32x2 packs; x duplicated-pair in shared so fma.rn.f32x2 does 2 outputs/op.
// ============================================================================
__global__ __launch_bounds__(256) void proj1_kernel(
    const float* __restrict__ X,
    const float* __restrict__ Wi1, const float* __restrict__ bi1,
    const float* __restrict__ Wp,  const float* __restrict__ bp)
{
    __shared__ __align__(16) unsigned long long xdup[8][16];  // 8 rows x 16 dup-pairs

    const int tid = threadIdx.x;
    const int j2  = tid & 127;   // output pair index (cols 2*j2, 2*j2+1 of 256)
    const int rr  = tid >> 7;    // 0..1

    unsigned long long wp_[16];
    unsigned long long bias;
    if (j2 < 96) {               // xi columns 0..191
        const int c0 = 2 * j2;
#pragma unroll
        for (int k = 0; k < 16; k++)
            wp_[k] = pk2(Wi1[k * 192 + c0], Wi1[k * 192 + c0 + 1]);
        bias = pk2(bi1[c0], bi1[c0 + 1]);
    } else {                     // xp columns 0..63
        const int c0 = 2 * j2 - 192;
#pragma unroll
        for (int k = 0; k < 16; k++)
            wp_[k] = pk2(Wp[k * 64 + c0], Wp[k * 64 + c0 + 1]);
        bias = pk2(bp[c0], bp[c0 + 1]);
    }

    for (size_t r0 = (size_t)blockIdx.x * 8; r0 < (size_t)NROWS;
         r0 += (size_t)gridDim.x * 8) {
        if (tid < 32) {  // load 8 rows x 16 floats, duplicate into pairs
            const float4* xs = (const float4*)(X + r0 * 16);
            float4 v = xs[tid];
            int row = tid >> 2, c4 = (tid & 3) * 4;
            xdup[row][c4 + 0] = pk2(v.x, v.x);
            xdup[row][c4 + 1] = pk2(v.y, v.y);
            xdup[row][c4 + 2] = pk2(v.z, v.z);
            xdup[row][c4 + 3] = pk2(v.w, v.w);
        }
        __syncthreads();
#pragma unroll
        for (int q = 0; q < 4; q++) {
            const int rw = rr * 4 + q;
            const ulonglong2* xr = (const ulonglong2*)&xdup[rw][0];
            unsigned long long acc = bias;
#pragma unroll
            for (int i = 0; i < 8; i++) {
                ulonglong2 u = xr[i];
                acc = ffma2(u.x, wp_[2 * i], acc);
                acc = ffma2(u.y, wp_[2 * i + 1], acc);
            }
            const size_t row = r0 + rw;
            if (j2 < 96)
                *(unsigned long long*)(g_xi + row * 192 + 2 * j2) = acc;
            else
                *(unsigned long long*)(g_aux + row * 64 + (2 * j2 - 192)) = acc;
        }
        __syncthreads();
    }
}

// ============================================================================
// proj2: xi2 = o1adj @ Wi2 + bi2  (1M x 64) @ (64 x 192)
// Block 192 = 2 row-groups x 96 output-pairs; weights (64 packs) in registers.
// ============================================================================
__global__ __launch_bounds__(192, 1) void proj2_kernel(
    const float* __restrict__ Wi2, const float* __restrict__ bi2)
{
    __shared__ __align__(16) unsigned long long xdup[8][64];  // 8 rows x 64 dup-pairs

    const int tid = threadIdx.x;
    const int j2  = tid % 96;    // cols 2*j2, 2*j2+1 of 192
    const int grp = tid / 96;    // rows grp*4 .. grp*4+3

    unsigned long long wp_[64];
#pragma unroll
    for (int k = 0; k < 64; k++)
        wp_[k] = pk2(Wi2[k * 192 + 2 * j2], Wi2[k * 192 + 2 * j2 + 1]);
    const unsigned long long bias = pk2(bi2[2 * j2], bi2[2 * j2 + 1]);

    for (size_t r0 = (size_t)blockIdx.x * 8; r0 < (size_t)NROWS;
         r0 += (size_t)gridDim.x * 8) {
        if (tid < 128) {  // load 8 rows x 64 floats, duplicate into pairs
            const float4* xs = (const float4*)(g_o1 + r0 * 64);
            float4 v = xs[tid];
            int row = tid >> 4, c4 = (tid & 15) * 4;
            xdup[row][c4 + 0] = pk2(v.x, v.x);
            xdup[row][c4 + 1] = pk2(v.y, v.y);
            xdup[row][c4 + 2] = pk2(v.z, v.z);
            xdup[row][c4 + 3] = pk2(v.w, v.w);
        }
        __syncthreads();
#pragma unroll
        for (int q = 0; q < 4; q++) {
            const int rw = grp * 4 + q;
            const ulonglong2* xr = (const ulonglong2*)&xdup[rw][0];
            unsigned long long a0 = bias, a1 = 0ull, a2 = 0ull, a3 = 0ull;
#pragma unroll
            for (int i = 0; i < 32; i += 4) {
                ulonglong2 u0 = xr[i], u1 = xr[i + 1], u2 = xr[i + 2], u3 = xr[i + 3];
                a0 = ffma2(u0.x, wp_[2 * i + 0], a0);
                a1 = ffma2(u0.y, wp_[2 * i + 1], a1);
                a2 = ffma2(u1.x, wp_[2 * i + 2], a2);
                a3 = ffma2(u1.y, wp_[2 * i + 3], a3);
                a0 = ffma2(u2.x, wp_[2 * i + 4], a0);
                a1 = ffma2(u2.y, wp_[2 * i + 5], a1);
                a2 = ffma2(u3.x, wp_[2 * i + 6], a2);
                a3 = ffma2(u3.y, wp_[2 * i + 7], a3);
            }
            a0 = fadd2(a0, a1); a2 = fadd2(a2, a3); a0 = fadd2(a0, a2);
            *(unsigned long long*)(g_xi + (r0 + rw) * 192 + 2 * j2) = a0;
        }
        __syncthreads();
    }
}

// ============================================================================
// GRU recurrence. 128 CTAs x 2 batch rows; 192 threads/row = 3 gates x 64 j.
// Thread (g,j) holds column j of {Whr,Whz,Whn}[g] as 32 f32x2 packs in regs.
// h in ping-pong shared (read as ulonglong2 broadcasts). Gate-n threads hold
// their own inn + aux and finalize h_new, so only r/z partials hit shared.
// xi/aux prefetched 2 steps ahead (~500 cyc) to cover DRAM latency.
// out[b][t][j] = h_new + 0.5*aux[b][t][j]
// layer2=0: aux=g_aux(xp), out=g_o1 ; layer2=1: aux=g_o1, out=g_aux(o2)
// ============================================================================
__global__ __launch_bounds__(384, 1) void gru_kernel(
    const float* __restrict__ Whr, const float* __restrict__ Whz,
    const float* __restrict__ Whn, const float* __restrict__ bhn,
    int layer2)
{
    const int tid = threadIdx.x;
    const int r   = tid / 192;       // row within CTA
    const int tr  = tid - r * 192;   // 0..191
    const int g   = tr >> 6;         // 0=r, 1=z, 2=n
    const int j   = tr & 63;
    const int b   = blockIdx.x * 2 + r;

    const float* aux = layer2 ? g_o1 : g_aux;
    float*       out = layer2 ? g_aux : g_o1;

    __shared__ __align__(16) double hbuf[2][2][32];  // [pingpong][row][64 floats]
    __shared__ float psum[2][2][64];                 // r/z partials (incl. xi)

    const float* W = (g == 0) ? Whr : (g == 1) ? Whz : Whn;
    unsigned long long wd[32];
#pragma unroll
    for (int i = 0; i < 32; i++)
        wd[i] = pk2(W[(2 * i) * 64 + j], W[(2 * i + 1) * 64 + j]);
    const float bn = (g == 2) ? bhn[j] : 0.0f;

    if (tr < 32) hbuf[0][r][tr] = 0.0;  // h0 = 0 (two packed float zeros)

    const float* xp = g_xi + ((size_t)b * TT) * 192 + tr;
    const float* ap = aux + ((size_t)b * TT) * 64 + j;
    float*       op = out + ((size_t)b * TT) * 64 + j;

    float xq0 = __ldg(xp), xq1 = __ldg(xp + 192);
    float aq0 = 0.f, aq1 = 0.f;
    if (g == 2) { aq0 = __ldg(ap); aq1 = __ldg(ap + 64); }
    xp += 2 * 192; ap += 2 * 64;
    __syncthreads();

    int buf = 0;
    for (int t = 0; t < TT; t++) {
        // prefetch t+2
        float xq2 = 0.f, aq2 = 0.f;
        if (t + 2 < TT) {
            xq2 = __ldg(xp);
            if (g == 2) aq2 = __ldg(ap);
        }
        xp += 192; ap += 64;

        // dot: sum_k h[k] * W[k][j]  (64 MACs as 32 packed FFMA2)
        const ulonglong2* hp = (const ulonglong2*)&hbuf[buf][r][0];
        unsigned long long a0 = 0ull, a1 = 0ull, a2 = 0ull, a3 = 0ull;
#pragma unroll
        for (int i = 0; i < 16; i += 4) {
            ulonglong2 u0 = hp[i], u1 = hp[i + 1], u2 = hp[i + 2], u3 = hp[i + 3];
            a0 = ffma2(u0.x, wd[2 * i + 0], a0);
            a1 = ffma2(u0.y, wd[2 * i + 1], a1);
            a2 = ffma2(u1.x, wd[2 * i + 2], a2);
            a3 = ffma2(u1.y, wd[2 * i + 3], a3);
            a0 = ffma2(u2.x, wd[2 * i + 4], a0);
            a1 = ffma2(u2.y, wd[2 * i + 5], a1);
            a2 = ffma2(u3.x, wd[2 * i + 6], a2);
            a3 = ffma2(u3.y, wd[2 * i + 7], a3);
        }
        a0 = fadd2(a0, a1); a2 = fadd2(a2, a3); a0 = fadd2(a0, a2);
        float lo, hi; unpk2(a0, lo, hi);
        const float dot = lo + hi;

        if (g < 2) psum[g][r][j] = dot + xq0;  // ir/iz folded in
        __syncthreads();

        if (g == 2) {
            const float rg    = sigmf(psum[0][r][j]);
            const float zg    = sigmf(psum[1][r][j]);
            const float hprev = ((const float*)&hbuf[buf][r][0])[j];
            const float n     = tanh_f(xq0 + rg * (dot + bn));  // xq0 = inn here
            const float hn    = n + zg * (hprev - n);
            ((float*)&hbuf[buf ^ 1][r][0])[j] = hn;
            *op = hn + 0.5f * aq0;
        }
        op += 64;
        __syncthreads();

        buf ^= 1;
        xq0 = xq1; xq1 = xq2;
        aq0 = aq1; aq1 = aq2;
    }
}

// ============================================================================
// Attention (softmax over T) + MLP head. One CTA per batch element.
// ============================================================================
__global__ __launch_bounds__(256) void att_mlp_kernel(
    const float* __restrict__ Wa, const float* __restrict__ ba,
    const float* __restrict__ W1, const float* __restrict__ b1,
    const float* __restrict__ W2, const float* __restrict__ b2,
    const float* __restrict__ W3, const float* __restrict__ b3,
    const float* __restrict__ W4, const float* __restrict__ b4,
    float* __restrict__ outp)
{
    const int b = blockIdx.x, tid = threadIdx.x;
    __shared__ float sc[TT];
    __shared__ float red[256];
    __shared__ float wash[64];
    __shared__ float att[64];
    __shared__ float h1s[128];
    __shared__ float h2s[64];
    __shared__ float h3s[32];

    if (tid < 64) wash[tid] = Wa[tid];
    __syncthreads();

    const float* o2b = g_aux + (size_t)b * TT * 64;

    // scores + local max
    float lmax = -1e30f;
    for (int t = tid; t < TT; t += 256) {
        const float4* rowp = (const float4*)(o2b + (size_t)t * 64);
        float s = 0.f;
#pragma unroll
        for (int i = 0; i < 16; i++) {
            float4 v = rowp[i];
            s += v.x * wash[4 * i] + v.y * wash[4 * i + 1]
               + v.z * wash[4 * i + 2] + v.w * wash[4 * i + 3];
        }
        s += ba[0];
        sc[t] = s;
        lmax = fmaxf(lmax, s);
    }
    red[tid] = lmax; __syncthreads();
    for (int off = 128; off > 0; off >>= 1) {
        if (tid < off) red[tid] = fmaxf(red[tid], red[tid + off]);
        __syncthreads();
    }
    const float m = red[0];
    __syncthreads();

    // exp + sum
    float lsum = 0.f;
    for (int t = tid; t < TT; t += 256) {
        float e = __expf(sc[t] - m);
        sc[t] = e;
        lsum += e;
    }
    red[tid] = lsum; __syncthreads();
    for (int off = 128; off > 0; off >>= 1) {
        if (tid < off) red[tid] += red[tid + off];
        __syncthreads();
    }
    const float inv = __fdividef(1.0f, red[0]);
    __syncthreads();

    // attended[j] = sum_t sc[t] * o2[t][j] * inv   (4 t-chunks per j)
    {
        const int j = tid & 63, ch = tid >> 6;
        const float* base = o2b + j;
        float c0 = 0.f, c1 = 0.f, c2 = 0.f, c3 = 0.f;
        const int t0 = ch * 1024;
        for (int t = t0; t < t0 + 1024; t += 4) {
            c0 += sc[t + 0] * base[(size_t)(t + 0) * 64];
            c1 += sc[t + 1] * base[(size_t)(t + 1) * 64];
            c2 += sc[t + 2] * base[(size_t)(t + 2) * 64];
            c3 += sc[t + 3] * base[(size_t)(t + 3) * 64];
        }
        red[tid] = (c0 + c1) + (c2 + c3);
    }
    __syncthreads();
    if (tid < 64)
        att[tid] = (red[tid] + red[tid + 64] + red[tid + 128] + red[tid + 192]) * inv;
    __syncthreads();

    // MLP head
    if (tid < 128) {
        float s = b1[tid];
#pragma unroll
        for (int k = 0; k < 64; k++) s += att[k] * W1[k * 128 + tid];
        h1s[tid] = fmaxf(s, 0.f);
    }
    __syncthreads();
    if (tid < 64) {
        float s = b2[tid];
#pragma unroll
        for (int k = 0; k < 128; k++) s += h1s[k] * W2[k * 64 + tid];
        h2s[tid] = fmaxf(s, 0.f);
    }
    __syncthreads();
    if (tid < 32) {
        float s = b3[tid];
#pragma unroll
        for (int k = 0; k < 64; k++) s += h2s[k] * W3[k * 32 + tid];
        h3s[tid] = fmaxf(s, 0.f);
    }
    __syncthreads();
    if (tid < 2) {
        float s = b4[tid];
#pragma unroll
        for (int k = 0; k < 32; k++) s += h3s[k] * W4[k * 2 + tid];
        outp[b * 2 + tid] = s;
    }
}

// ============================================================================
extern "C" void kernel_launch(void* const* d_in, const int* in_sizes, int n_in,
                              void* d_out, int out_size)
{
    const float* x    = (const float*)d_in[0];
    const float* Wi1  = (const float*)d_in[1];
    const float* bi1  = (const float*)d_in[2];
    const float* Whr1 = (const float*)d_in[3];
    const float* Whz1 = (const float*)d_in[4];
    const float* Whn1 = (const float*)d_in[5];
    const float* bhn1 = (const float*)d_in[6];
    const float* Wi2  = (const float*)d_in[7];
    const float* bi2  = (const float*)d_in[8];
    const float* Whr2 = (const float*)d_in[9];
    const float* Whz2 = (const float*)d_in[10];
    const float* Whn2 = (const float*)d_in[11];
    const float* bhn2 = (const float*)d_in[12];
    const float* Wp   = (const float*)d_in[13];
    const float* bp   = (const float*)d_in[14];
    const float* Wa   = (const float*)d_in[15];
    const float* ba   = (const float*)d_in[16];
    const float* W1   = (const float*)d_in[17];
    const float* b1   = (const float*)d_in[18];
    const float* W2   = (const float*)d_in[19];
    const float* b2   = (const float*)d_in[20];
    const float* W3   = (const float*)d_in[21];
    const float* b3   = (const float*)d_in[22];
    const float* W4   = (const float*)d_in[23];
    const float* b4   = (const float*)d_in[24];
    float* outp = (float*)d_out;

    // 1. xi1 = x@Wi1+bi1 -> g_xi ; xp = x@Wp+bp -> g_aux
    proj1_kernel<<<592, 256>>>(x, Wi1, bi1, Wp, bp);
    // 2. GRU layer 1 -> g_o1 = gru(x) + 0.5*xp
    gru_kernel<<<128, 384>>>(Whr1, Whz1, Whn1, bhn1, 0);
    // 3. xi2 = o1adj@Wi2+bi2 -> g_xi (reuse)
    proj2_kernel<<<148, 192>>>(Wi2, bi2);
    // 4. GRU layer 2 -> g_aux = gru(o1adj) + 0.5*o1adj  (= o2)
    gru_kernel<<<128, 384>>>(Whr2, Whz2, Whn2, bhn2, 1);
    // 5. attention softmax + MLP head -> out (B,2)
    att_mlp_kernel<<<BB, 256>>>(Wa, ba, W1, b1, W2, b2, W3, b3, W4, b4, outp);
}

// round 5
// speedup vs baseline: 1.1360x; 1.1360x over previous
#include <cuda_runtime.h>
#include <cuda_bf16.h>
#include <cstdint>

// Problem constants (fixed by the reference)
#define BB 256
#define TT 4096
#define FF 16
#define HH 64
#define NROWS (256*4096)   // 1048576 rows of (b,t)

// -------------------- scratch (device globals; no allocs allowed) -----------
__device__ float g_xi [(size_t)NROWS * 192];  // xi1, then reused as xi2 (805 MB)
__device__ float g_aux[(size_t)NROWS * 64];   // xp, then reused as o2   (268 MB)
__device__ float g_o1 [(size_t)NROWS * 64];   // o1adj                   (268 MB)

// -------------------- packed f32x2 helpers ----------------------------------
__device__ __forceinline__ unsigned long long pk2(float lo, float hi) {
    unsigned long long d;
    asm("mov.b64 %0, {%1, %2};" : "=l"(d) : "f"(lo), "f"(hi));
    return d;
}
__device__ __forceinline__ void unpk2(unsigned long long v, float& lo, float& hi) {
    asm("mov.b64 {%0, %1}, %2;" : "=f"(lo), "=f"(hi) : "l"(v));
}
__device__ __forceinline__ unsigned long long ffma2(unsigned long long a,
                                                    unsigned long long b,
                                                    unsigned long long c) {
    unsigned long long d;
    asm("fma.rn.f32x2 %0, %1, %2, %3;" : "=l"(d) : "l"(a), "l"(b), "l"(c));
    return d;
}
__device__ __forceinline__ unsigned long long fadd2(unsigned long long a,
                                                    unsigned long long b) {
    unsigned long long d;
    asm("add.rn.f32x2 %0, %1, %2;" : "=l"(d) : "l"(a), "l"(b));
    return d;
}

// HW tanh (MUFU.TANH): ~2^-11 max error — used for the r/z sigmoids only.
__device__ __forceinline__ float tanh_mufu(float x) {
    float y;
    asm("tanh.approx.f32 %0, %1;" : "=f"(y) : "f"(x));
    return y;
}
__device__ __forceinline__ float sigm_mufu(float x) {
    return fmaf(0.5f, tanh_mufu(0.5f * x), 0.5f);
}
// Accurate tanh for the n-gate (feeds h directly)
__device__ __forceinline__ float tanh_f(float x) {
    return __fdividef(2.0f, 1.0f + __expf(-2.0f * x)) - 1.0f;
}

// ============================================================================
// proj1: for each (b,t) row: xi1 = x@Wi1 + bi1 (192), xp = x@Wp + bp (64)
// ============================================================================
__global__ __launch_bounds__(256) void proj1_kernel(
    const float* __restrict__ X,
    const float* __restrict__ Wi1, const float* __restrict__ bi1,
    const float* __restrict__ Wp,  const float* __restrict__ bp)
{
    __shared__ __align__(16) unsigned long long xdup[8][16];  // 8 rows x 16 dup-pairs

    const int tid = threadIdx.x;
    const int j2  = tid & 127;   // output pair index
    const int rr  = tid >> 7;    // 0..1

    unsigned long long wp_[16];
    unsigned long long bias;
    if (j2 < 96) {               // xi columns 0..191
        const int c0 = 2 * j2;
#pragma unroll
        for (int k = 0; k < 16; k++)
            wp_[k] = pk2(Wi1[k * 192 + c0], Wi1[k * 192 + c0 + 1]);
        bias = pk2(bi1[c0], bi1[c0 + 1]);
    } else {                     // xp columns 0..63
        const int c0 = 2 * j2 - 192;
#pragma unroll
        for (int k = 0; k < 16; k++)
            wp_[k] = pk2(Wp[k * 64 + c0], Wp[k * 64 + c0 + 1]);
        bias = pk2(bp[c0], bp[c0 + 1]);
    }

    for (size_t r0 = (size_t)blockIdx.x * 8; r0 < (size_t)NROWS;
         r0 += (size_t)gridDim.x * 8) {
        if (tid < 32) {
            const float4* xs = (const float4*)(X + r0 * 16);
            float4 v = xs[tid];
            int row = tid >> 2, c4 = (tid & 3) * 4;
            xdup[row][c4 + 0] = pk2(v.x, v.x);
            xdup[row][c4 + 1] = pk2(v.y, v.y);
            xdup[row][c4 + 2] = pk2(v.z, v.z);
            xdup[row][c4 + 3] = pk2(v.w, v.w);
        }
        __syncthreads();
#pragma unroll
        for (int q = 0; q < 4; q++) {
            const int rw = rr * 4 + q;
            const ulonglong2* xr = (const ulonglong2*)&xdup[rw][0];
            unsigned long long acc = bias;
#pragma unroll
            for (int i = 0; i < 8; i++) {
                ulonglong2 u = xr[i];
                acc = ffma2(u.x, wp_[2 * i], acc);
                acc = ffma2(u.y, wp_[2 * i + 1], acc);
            }
            const size_t row = r0 + rw;
            if (j2 < 96)
                *(unsigned long long*)(g_xi + row * 192 + 2 * j2) = acc;
            else
                *(unsigned long long*)(g_aux + row * 64 + (2 * j2 - 192)) = acc;
        }
        __syncthreads();
    }
}

// ============================================================================
// proj2: xi2 = o1adj @ Wi2 + bi2  (1M x 64) @ (64 x 192)
// ============================================================================
__global__ __launch_bounds__(192, 1) void proj2_kernel(
    const float* __restrict__ Wi2, const float* __restrict__ bi2)
{
    __shared__ __align__(16) unsigned long long xdup[8][64];

    const int tid = threadIdx.x;
    const int j2  = tid % 96;
    const int grp = tid / 96;

    unsigned long long wp_[64];
#pragma unroll
    for (int k = 0; k < 64; k++)
        wp_[k] = pk2(Wi2[k * 192 + 2 * j2], Wi2[k * 192 + 2 * j2 + 1]);
    const unsigned long long bias = pk2(bi2[2 * j2], bi2[2 * j2 + 1]);

    for (size_t r0 = (size_t)blockIdx.x * 8; r0 < (size_t)NROWS;
         r0 += (size_t)gridDim.x * 8) {
        if (tid < 128) {
            const float4* xs = (const float4*)(g_o1 + r0 * 64);
            float4 v = xs[tid];
            int row = tid >> 4, c4 = (tid & 15) * 4;
            xdup[row][c4 + 0] = pk2(v.x, v.x);
            xdup[row][c4 + 1] = pk2(v.y, v.y);
            xdup[row][c4 + 2] = pk2(v.z, v.z);
            xdup[row][c4 + 3] = pk2(v.w, v.w);
        }
        __syncthreads();
#pragma unroll
        for (int q = 0; q < 4; q++) {
            const int rw = grp * 4 + q;
            const ulonglong2* xr = (const ulonglong2*)&xdup[rw][0];
            unsigned long long a0 = bias, a1 = 0ull, a2 = 0ull, a3 = 0ull;
#pragma unroll
            for (int i = 0; i < 32; i += 4) {
                ulonglong2 u0 = xr[i], u1 = xr[i + 1], u2 = xr[i + 2], u3 = xr[i + 3];
                a0 = ffma2(u0.x, wp_[2 * i + 0], a0);
                a1 = ffma2(u0.y, wp_[2 * i + 1], a1);
                a2 = ffma2(u1.x, wp_[2 * i + 2], a2);
                a3 = ffma2(u1.y, wp_[2 * i + 3], a3);
                a0 = ffma2(u2.x, wp_[2 * i + 4], a0);
                a1 = ffma2(u2.y, wp_[2 * i + 5], a1);
                a2 = ffma2(u3.x, wp_[2 * i + 6], a2);
                a3 = ffma2(u3.y, wp_[2 * i + 7], a3);
            }
            a0 = fadd2(a0, a1); a2 = fadd2(a2, a3); a0 = fadd2(a0, a2);
            *(unsigned long long*)(g_xi + (r0 + rw) * 192 + 2 * j2) = a0;
        }
        __syncthreads();
    }
}

// ============================================================================
// GRU recurrence. 128 CTAs x 2 batch rows; 192 threads/row = 3 gates x 64 j.
// KEY CHANGE vs R3: true 4-step-deep register prefetch pipeline. The t-loop is
// unrolled x4 over a 4-slot register queue; slot u is consumed at step tb+u and
// its register is refilled by the LDG for step tb+u+4. No register shifts ->
// the LDG's first consumer is 4 steps (~1400 cyc) later, fully covering DRAM
// latency (R3's shift-queue degenerated to 1-step distance and clamped every
// step to ~DRAM latency).
// Also: r/z sigmoids via MUFU.TANH (1 MUFU vs ~44-cyc exp/div chain).
// ============================================================================
__global__ __launch_bounds__(384, 1) void gru_kernel(
    const float* __restrict__ Whr, const float* __restrict__ Whz,
    const float* __restrict__ Whn, const float* __restrict__ bhn,
    int layer2)
{
    const int tid = threadIdx.x;
    const int r   = tid / 192;       // row within CTA
    const int tr  = tid - r * 192;   // 0..191
    const int g   = tr >> 6;         // 0=r, 1=z, 2=n
    const int j   = tr & 63;
    const int b   = blockIdx.x * 2 + r;

    const float* aux = layer2 ? g_o1 : g_aux;
    float*       out = layer2 ? g_aux : g_o1;

    __shared__ __align__(16) float hbuf[2][2][64];   // [pingpong][row][64]
    __shared__ float psum[2][2][64];                 // r/z partials (incl. xi)

    const float* W = (g == 0) ? Whr : (g == 1) ? Whz : Whn;
    unsigned long long wd[32];
#pragma unroll
    for (int i = 0; i < 32; i++)
        wd[i] = pk2(W[(2 * i) * 64 + j], W[(2 * i + 1) * 64 + j]);
    const float bn = (g == 2) ? bhn[j] : 0.0f;

    if (tr < 64) hbuf[0][r][tr] = 0.0f;  // h0 = 0

    const float* xp = g_xi + ((size_t)b * TT) * 192 + tr;
    const float* ap = aux + ((size_t)b * TT) * 64 + j;
    float*       op = out + ((size_t)b * TT) * 64 + j;

    // 4-deep register pipeline preload (steps 0..3)
    float xq[4];
    float aq[4] = {0.f, 0.f, 0.f, 0.f};
#pragma unroll
    for (int u = 0; u < 4; u++) {
        xq[u] = __ldg(xp + u * 192);
        if (g == 2) aq[u] = __ldg(ap + u * 64);
    }
    xp += 4 * 192; ap += 4 * 64;
    __syncthreads();

    int buf = 0;
    for (int tb = 0; tb < TT; tb += 4) {
        const bool pf = (tb + 4) < TT;   // uniform: all 4 prefetches valid or none
#pragma unroll
        for (int u = 0; u < 4; u++) {
            const float xcur = xq[u];
            const float acur = aq[u];
            // refill slot u with step tb+u+4 (consumed 4 steps from now)
            if (pf) {
                xq[u] = __ldg(xp);
                if (g == 2) aq[u] = __ldg(ap);
            }
            xp += 192; ap += 64;

            // dot: sum_k h[k] * W[k][j]  (64 MACs as 32 packed FFMA2)
            const ulonglong2* hp = (const ulonglong2*)&hbuf[buf][r][0];
            unsigned long long a0 = 0ull, a1 = 0ull, a2 = 0ull, a3 = 0ull;
#pragma unroll
            for (int i = 0; i < 16; i += 4) {
                ulonglong2 u0 = hp[i], u1 = hp[i + 1], u2 = hp[i + 2], u3 = hp[i + 3];
                a0 = ffma2(u0.x, wd[2 * i + 0], a0);
                a1 = ffma2(u0.y, wd[2 * i + 1], a1);
                a2 = ffma2(u1.x, wd[2 * i + 2], a2);
                a3 = ffma2(u1.y, wd[2 * i + 3], a3);
                a0 = ffma2(u2.x, wd[2 * i + 4], a0);
                a1 = ffma2(u2.y, wd[2 * i + 5], a1);
                a2 = ffma2(u3.x, wd[2 * i + 6], a2);
                a3 = ffma2(u3.y, wd[2 * i + 7], a3);
            }
            a0 = fadd2(a0, a1); a2 = fadd2(a2, a3); a0 = fadd2(a0, a2);
            float lo, hi; unpk2(a0, lo, hi);
            const float dot = lo + hi;

            if (g < 2) psum[g][r][j] = dot + xcur;  // ir/iz folded in
            const float dnb = dot + bn;             // n-gate: pre-barrier add
            __syncthreads();

            if (g == 2) {
                const float rg    = sigm_mufu(psum[0][r][j]);
                const float zg    = sigm_mufu(psum[1][r][j]);
                const float hprev = hbuf[buf][r][j];
                const float n     = tanh_f(xcur + rg * dnb);  // xcur = inn here
                const float hn    = n + zg * (hprev - n);
                hbuf[buf ^ 1][r][j] = hn;
                *op = hn + 0.5f * acur;
            }
            op += 64;
            __syncthreads();

            buf ^= 1;
        }
    }
}

// ============================================================================
// Attention (softmax over T) + MLP head. One CTA per batch element.
// ============================================================================
__global__ __launch_bounds__(256) void att_mlp_kernel(
    const float* __restrict__ Wa, const float* __restrict__ ba,
    const float* __restrict__ W1, const float* __restrict__ b1,
    const float* __restrict__ W2, const float* __restrict__ b2,
    const float* __restrict__ W3, const float* __restrict__ b3,
    const float* __restrict__ W4, const float* __restrict__ b4,
    float* __restrict__ outp)
{
    const int b = blockIdx.x, tid = threadIdx.x;
    __shared__ float sc[TT];
    __shared__ float red[256];
    __shared__ float wash[64];
    __shared__ float att[64];
    __shared__ float h1s[128];
    __shared__ float h2s[64];
    __shared__ float h3s[32];

    if (tid < 64) wash[tid] = Wa[tid];
    __syncthreads();

    const float* o2b = g_aux + (size_t)b * TT * 64;

    // scores + local max
    float lmax = -1e30f;
    for (int t = tid; t < TT; t += 256) {
        const float4* rowp = (const float4*)(o2b + (size_t)t * 64);
        float s = 0.f;
#pragma unroll
        for (int i = 0; i < 16; i++) {
            float4 v = rowp[i];
            s += v.x * wash[4 * i] + v.y * wash[4 * i + 1]
               + v.z * wash[4 * i + 2] + v.w * wash[4 * i + 3];
        }
        s += ba[0];
        sc[t] = s;
        lmax = fmaxf(lmax, s);
    }
    red[tid] = lmax; __syncthreads();
    for (int off = 128; off > 0; off >>= 1) {
        if (tid < off) red[tid] = fmaxf(red[tid], red[tid + off]);
        __syncthreads();
    }
    const float m = red[0];
    __syncthreads();

    // exp + sum
    float lsum = 0.f;
    for (int t = tid; t < TT; t += 256) {
        float e = __expf(sc[t] - m);
        sc[t] = e;
        lsum += e;
    }
    red[tid] = lsum; __syncthreads();
    for (int off = 128; off > 0; off >>= 1) {
        if (tid < off) red[tid] += red[tid + off];
        __syncthreads();
    }
    const float inv = __fdividef(1.0f, red[0]);
    __syncthreads();

    // attended[j] = sum_t sc[t] * o2[t][j] * inv
    {
        const int j = tid & 63, ch = tid >> 6;
        const float* base = o2b + j;
        float c0 = 0.f, c1 = 0.f, c2 = 0.f, c3 = 0.f;
        const int t0 = ch * 1024;
        for (int t = t0; t < t0 + 1024; t += 4) {
            c0 += sc[t + 0] * base[(size_t)(t + 0) * 64];
            c1 += sc[t + 1] * base[(size_t)(t + 1) * 64];
            c2 += sc[t + 2] * base[(size_t)(t + 2) * 64];
            c3 += sc[t + 3] * base[(size_t)(t + 3) * 64];
        }
        red[tid] = (c0 + c1) + (c2 + c3);
    }
    __syncthreads();
    if (tid < 64)
        att[tid] = (red[tid] + red[tid + 64] + red[tid + 128] + red[tid + 192]) * inv;
    __syncthreads();

    // MLP head
    if (tid < 128) {
        float s = b1[tid];
#pragma unroll
        for (int k = 0; k < 64; k++) s += att[k] * W1[k * 128 + tid];
        h1s[tid] = fmaxf(s, 0.f);
    }
    __syncthreads();
    if (tid < 64) {
        float s = b2[tid];
#pragma unroll
        for (int k = 0; k < 128; k++) s += h1s[k] * W2[k * 64 + tid];
        h2s[tid] = fmaxf(s, 0.f);
    }
    __syncthreads();
    if (tid < 32) {
        float s = b3[tid];
#pragma unroll
        for (int k = 0; k < 64; k++) s += h2s[k] * W3[k * 32 + tid];
        h3s[tid] = fmaxf(s, 0.f);
    }
    __syncthreads();
    if (tid < 2) {
        float s = b4[tid];
#pragma unroll
        for (int k = 0; k < 32; k++) s += h3s[k] * W4[k * 2 + tid];
        outp[b * 2 + tid] = s;
    }
}

// ============================================================================
extern "C" void kernel_launch(void* const* d_in, const int* in_sizes, int n_in,
                              void* d_out, int out_size)
{
    const float* x    = (const float*)d_in[0];
    const float* Wi1  = (const float*)d_in[1];
    const float* bi1  = (const float*)d_in[2];
    const float* Whr1 = (const float*)d_in[3];
    const float* Whz1 = (const float*)d_in[4];
    const float* Whn1 = (const float*)d_in[5];
    const float* bhn1 = (const float*)d_in[6];
    const float* Wi2  = (const float*)d_in[7];
    const float* bi2  = (const float*)d_in[8];
    const float* Whr2 = (const float*)d_in[9];
    const float* Whz2 = (const float*)d_in[10];
    const float* Whn2 = (const float*)d_in[11];
    const float* bhn2 = (const float*)d_in[12];
    const float* Wp   = (const float*)d_in[13];
    const float* bp   = (const float*)d_in[14];
    const float* Wa   = (const float*)d_in[15];
    const float* ba   = (const float*)d_in[16];
    const float* W1   = (const float*)d_in[17];
    const float* b1   = (const float*)d_in[18];
    const float* W2   = (const float*)d_in[19];
    const float* b2   = (const float*)d_in[20];
    const float* W3   = (const float*)d_in[21];
    const float* b3   = (const float*)d_in[22];
    const float* W4   = (const float*)d_in[23];
    const float* b4   = (const float*)d_in[24];
    float* outp = (float*)d_out;

    // 1. xi1 = x@Wi1+bi1 -> g_xi ; xp = x@Wp+bp -> g_aux
    proj1_kernel<<<592, 256>>>(x, Wi1, bi1, Wp, bp);
    // 2. GRU layer 1 -> g_o1 = gru(x) + 0.5*xp
    gru_kernel<<<128, 384>>>(Whr1, Whz1, Whn1, bhn1, 0);
    // 3. xi2 = o1adj@Wi2+bi2 -> g_xi (reuse)
    proj2_kernel<<<148, 192>>>(Wi2, bi2);
    // 4. GRU layer 2 -> g_aux = gru(o1adj) + 0.5*o1adj  (= o2)
    gru_kernel<<<128, 384>>>(Whr2, Whz2, Whn2, bhn2, 1);
    // 5. attention softmax + MLP head -> out (B,2)
    att_mlp_kernel<<<BB, 256>>>(Wa, ba, W1, b1, W2, b2, W3, b3, W4, b4, outp);
}

// round 7
// speedup vs baseline: 1.4413x; 1.2687x over previous
#include <cuda_runtime.h>
#include <cuda_bf16.h>
#include <cstdint>

// Problem constants (fixed by the reference)
#define BB 256
#define TT 4096
#define FF 16
#define HH 64
#define NROWS (256*4096)   // 1048576 rows of (b,t)

// -------------------- scratch (device globals; no allocs allowed) -----------
__device__ float g_xi [(size_t)NROWS * 192];  // xi1, then reused as xi2 (805 MB)
__device__ float g_aux[(size_t)NROWS * 64];   // xp, then reused as o2   (268 MB)
__device__ float g_o1 [(size_t)NROWS * 64];   // o1adj                   (268 MB)

// -------------------- packed f32x2 helpers ----------------------------------
__device__ __forceinline__ unsigned long long pk2(float lo, float hi) {
    unsigned long long d;
    asm("mov.b64 %0, {%1, %2};" : "=l"(d) : "f"(lo), "f"(hi));
    return d;
}
__device__ __forceinline__ void unpk2(unsigned long long v, float& lo, float& hi) {
    asm("mov.b64 {%0, %1}, %2;" : "=f"(lo), "=f"(hi) : "l"(v));
}
__device__ __forceinline__ unsigned long long ffma2(unsigned long long a,
                                                    unsigned long long b,
                                                    unsigned long long c) {
    unsigned long long d;
    asm("fma.rn.f32x2 %0, %1, %2, %3;" : "=l"(d) : "l"(a), "l"(b), "l"(c));
    return d;
}
__device__ __forceinline__ unsigned long long fadd2(unsigned long long a,
                                                    unsigned long long b) {
    unsigned long long d;
    asm("add.rn.f32x2 %0, %1, %2;" : "=l"(d) : "l"(a), "l"(b));
    return d;
}

// HW tanh (MUFU.TANH): ~2^-11 max error — used for the r/z sigmoids only.
__device__ __forceinline__ float tanh_mufu(float x) {
    float y;
    asm("tanh.approx.f32 %0, %1;" : "=f"(y) : "f"(x));
    return y;
}
__device__ __forceinline__ float sigm_mufu(float x) {
    return fmaf(0.5f, tanh_mufu(0.5f * x), 0.5f);
}
// Accurate tanh for the n-gate (feeds h directly)
__device__ __forceinline__ float tanh_f(float x) {
    return __fdividef(2.0f, 1.0f + __expf(-2.0f * x)) - 1.0f;
}

// ============================================================================
// proj1: for each (b,t) row: xi1 = x@Wi1 + bi1 (192), xp = x@Wp + bp (64)
// ============================================================================
__global__ __launch_bounds__(256) void proj1_kernel(
    const float* __restrict__ X,
    const float* __restrict__ Wi1, const float* __restrict__ bi1,
    const float* __restrict__ Wp,  const float* __restrict__ bp)
{
    __shared__ __align__(16) unsigned long long xdup[8][16];  // 8 rows x 16 dup-pairs

    const int tid = threadIdx.x;
    const int j2  = tid & 127;   // output pair index
    const int rr  = tid >> 7;    // 0..1

    unsigned long long wp_[16];
    unsigned long long bias;
    if (j2 < 96) {               // xi columns 0..191
        const int c0 = 2 * j2;
#pragma unroll
        for (int k = 0; k < 16; k++)
            wp_[k] = pk2(Wi1[k * 192 + c0], Wi1[k * 192 + c0 + 1]);
        bias = pk2(bi1[c0], bi1[c0 + 1]);
    } else {                     // xp columns 0..63
        const int c0 = 2 * j2 - 192;
#pragma unroll
        for (int k = 0; k < 16; k++)
            wp_[k] = pk2(Wp[k * 64 + c0], Wp[k * 64 + c0 + 1]);
        bias = pk2(bp[c0], bp[c0 + 1]);
    }

    for (size_t r0 = (size_t)blockIdx.x * 8; r0 < (size_t)NROWS;
         r0 += (size_t)gridDim.x * 8) {
        if (tid < 32) {
            const float4* xs = (const float4*)(X + r0 * 16);
            float4 v = xs[tid];
            int row = tid >> 2, c4 = (tid & 3) * 4;
            xdup[row][c4 + 0] = pk2(v.x, v.x);
            xdup[row][c4 + 1] = pk2(v.y, v.y);
            xdup[row][c4 + 2] = pk2(v.z, v.z);
            xdup[row][c4 + 3] = pk2(v.w, v.w);
        }
        __syncthreads();
#pragma unroll
        for (int q = 0; q < 4; q++) {
            const int rw = rr * 4 + q;
            const ulonglong2* xr = (const ulonglong2*)&xdup[rw][0];
            unsigned long long acc = bias;
#pragma unroll
            for (int i = 0; i < 8; i++) {
                ulonglong2 u = xr[i];
                acc = ffma2(u.x, wp_[2 * i], acc);
                acc = ffma2(u.y, wp_[2 * i + 1], acc);
            }
            const size_t row = r0 + rw;
            if (j2 < 96)
                *(unsigned long long*)(g_xi + row * 192 + 2 * j2) = acc;
            else
                *(unsigned long long*)(g_aux + row * 64 + (2 * j2 - 192)) = acc;
        }
        __syncthreads();
    }
}

// ============================================================================
// proj2: xi2 = o1adj @ Wi2 + bi2  (1M x 64) @ (64 x 192)
// launch_bounds(192,2): 2 CTAs/SM so the LDS/store latency of one CTA hides
// behind the other's FFMA2 issue.
// ============================================================================
__global__ __launch_bounds__(192, 2) void proj2_kernel(
    const float* __restrict__ Wi2, const float* __restrict__ bi2)
{
    __shared__ __align__(16) unsigned long long xdup[8][64];

    const int tid = threadIdx.x;
    const int j2  = tid % 96;
    const int grp = tid / 96;

    unsigned long long wp_[64];
#pragma unroll
    for (int k = 0; k < 64; k++)
        wp_[k] = pk2(Wi2[k * 192 + 2 * j2], Wi2[k * 192 + 2 * j2 + 1]);
    const unsigned long long bias = pk2(bi2[2 * j2], bi2[2 * j2 + 1]);

    for (size_t r0 = (size_t)blockIdx.x * 8; r0 < (size_t)NROWS;
         r0 += (size_t)gridDim.x * 8) {
        if (tid < 128) {
            const float4* xs = (const float4*)(g_o1 + r0 * 64);
            float4 v = xs[tid];
            int row = tid >> 4, c4 = (tid & 15) * 4;
            xdup[row][c4 + 0] = pk2(v.x, v.x);
            xdup[row][c4 + 1] = pk2(v.y, v.y);
            xdup[row][c4 + 2] = pk2(v.z, v.z);
            xdup[row][c4 + 3] = pk2(v.w, v.w);
        }
        __syncthreads();
#pragma unroll
        for (int q = 0; q < 4; q++) {
            const int rw = grp * 4 + q;
            const ulonglong2* xr = (const ulonglong2*)&xdup[rw][0];
            unsigned long long a0 = bias, a1 = 0ull, a2 = 0ull, a3 = 0ull;
#pragma unroll
            for (int i = 0; i < 32; i += 4) {
                ulonglong2 u0 = xr[i], u1 = xr[i + 1], u2 = xr[i + 2], u3 = xr[i + 3];
                a0 = ffma2(u0.x, wp_[2 * i + 0], a0);
                a1 = ffma2(u0.y, wp_[2 * i + 1], a1);
                a2 = ffma2(u1.x, wp_[2 * i + 2], a2);
                a3 = ffma2(u1.y, wp_[2 * i + 3], a3);
                a0 = ffma2(u2.x, wp_[2 * i + 4], a0);
                a1 = ffma2(u2.y, wp_[2 * i + 5], a1);
                a2 = ffma2(u3.x, wp_[2 * i + 6], a2);
                a3 = ffma2(u3.y, wp_[2 * i + 7], a3);
            }
            a0 = fadd2(a0, a1); a2 = fadd2(a2, a3); a0 = fadd2(a0, a2);
            *(unsigned long long*)(g_xi + (r0 + rw) * 192 + 2 * j2) = a0;
        }
        __syncthreads();
    }
}

// ============================================================================
// GRU recurrence — R5 restructure.
// One CTA per batch row, 128 threads = 64 columns x 2 k-halves.
// Thread (j,s) holds rows k in [32s,32s+32) of ALL THREE hidden kernels for
// column j (48 f32x2 packs). Per step:
//   - 48 FFMA2 partial dots (6 independent chains)
//   - one shfl_xor(1) per gate to combine the two halves (no shared psum)
//   - EVERY thread computes r,z,n,hn for its column (redundant across s, but
//     no serial tail: all 4 warps do the gate math concurrently)
//   - hprev lives in a register (same thread owns column j for all t)
//   - s=0 writes h to ping-pong shared (next step's dots), s=1 writes output
//   - ONE __syncthreads per step (4 warps)
// h halves stored at offsets 0 / 36 floats (+16B pad) -> conflict-free LDS.128.
// xi (ir,iz,inn) + aux prefetched 4 steps deep in register queues.
// ============================================================================
__global__ __launch_bounds__(128, 2) void gru_kernel(
    const float* __restrict__ Whr, const float* __restrict__ Whz,
    const float* __restrict__ Whn, const float* __restrict__ bhn,
    int layer2)
{
    const int tid = threadIdx.x;
    const int j   = tid >> 1;     // 0..63 output column
    const int s   = tid & 1;      // k-half
    const int b   = blockIdx.x;
    const int k0  = 32 * s;

    const float* aux = layer2 ? g_o1 : g_aux;
    float*       out = layer2 ? g_aux : g_o1;

    __shared__ __align__(16) float hbuf[2][72];  // halves at [0,32) and [36,68)

    unsigned long long wr_[16], wz_[16], wn_[16];
#pragma unroll
    for (int i = 0; i < 16; i++) {
        wr_[i] = pk2(Whr[(k0 + 2 * i) * 64 + j], Whr[(k0 + 2 * i + 1) * 64 + j]);
        wz_[i] = pk2(Whz[(k0 + 2 * i) * 64 + j], Whz[(k0 + 2 * i + 1) * 64 + j]);
        wn_[i] = pk2(Whn[(k0 + 2 * i) * 64 + j], Whn[(k0 + 2 * i + 1) * 64 + j]);
    }
    const float bn   = bhn[j];
    const int   jpad = j + ((j >> 5) << 2);   // j<32 -> j ; j>=32 -> j+4

    if (tid < 72) hbuf[0][tid] = 0.0f;        // h0 = 0 (covers both halves+pad)

    const float* pr = g_xi + (size_t)b * TT * 192 + j;
    const float* pz = pr + 64;
    const float* pn = pr + 128;
    const float* pa = aux + (size_t)b * TT * 64 + j;
    float*       op = out + (size_t)b * TT * 64 + j;

    // 4-deep register prefetch queues (slot u refilled with step tb+u+4)
    float qr[4], qz[4], qn[4], qa[4] = {0.f, 0.f, 0.f, 0.f};
#pragma unroll
    for (int u = 0; u < 4; u++) {
        qr[u] = __ldg(pr + u * 192);
        qz[u] = __ldg(pz + u * 192);
        qn[u] = __ldg(pn + u * 192);
        if (s) qa[u] = __ldg(pa + u * 64);
    }
    pr += 4 * 192; pz += 4 * 192; pn += 4 * 192; pa += 4 * 64;

    float hprev = 0.0f;
    __syncthreads();

    int buf = 0;
    for (int tb = 0; tb < TT; tb += 4) {
        const bool pf = (tb + 4) < TT;
#pragma unroll
        for (int u = 0; u < 4; u++) {
            const float ir = qr[u], iz = qz[u], inn = qn[u], av = qa[u];
            if (pf) {
                qr[u] = __ldg(pr); qz[u] = __ldg(pz); qn[u] = __ldg(pn);
                if (s) qa[u] = __ldg(pa);
            }
            pr += 192; pz += 192; pn += 192; pa += 64;

            // partial dots over this thread's k-half (32 MACs/gate = 16 FFMA2)
            const ulonglong2* hp = (const ulonglong2*)&hbuf[buf][36 * s];
            unsigned long long r0 = 0ull, r1 = 0ull, z0 = 0ull, z1 = 0ull,
                               n0 = 0ull, n1 = 0ull;
#pragma unroll
            for (int i = 0; i < 8; i++) {
                ulonglong2 h2 = hp[i];
                r0 = ffma2(h2.x, wr_[2 * i],     r0);
                r1 = ffma2(h2.y, wr_[2 * i + 1], r1);
                z0 = ffma2(h2.x, wz_[2 * i],     z0);
                z1 = ffma2(h2.y, wz_[2 * i + 1], z1);
                n0 = ffma2(h2.x, wn_[2 * i],     n0);
                n1 = ffma2(h2.y, wn_[2 * i + 1], n1);
            }
            float lo, hi;
            r0 = fadd2(r0, r1); unpk2(r0, lo, hi); float dr = lo + hi;
            z0 = fadd2(z0, z1); unpk2(z0, lo, hi); float dz = lo + hi;
            n0 = fadd2(n0, n1); unpk2(n0, lo, hi); float dn = lo + hi;
            dr += __shfl_xor_sync(0xffffffffu, dr, 1);
            dz += __shfl_xor_sync(0xffffffffu, dz, 1);
            dn += __shfl_xor_sync(0xffffffffu, dn, 1);

            const float rg = sigm_mufu(ir + dr);
            const float zg = sigm_mufu(iz + dz);
            const float n  = tanh_f(inn + rg * (dn + bn));
            const float hn = n + zg * (hprev - n);
            hprev = hn;
            if (s) *op = hn + 0.5f * av;          // s=1: write output
            else   hbuf[buf ^ 1][jpad] = hn;      // s=0: publish h for t+1
            op += 64;
            __syncthreads();                      // single barrier per step
            buf ^= 1;
        }
    }
}

// ============================================================================
// Attention (softmax over T) + MLP head. One CTA per batch element.
// ============================================================================
__global__ __launch_bounds__(256) void att_mlp_kernel(
    const float* __restrict__ Wa, const float* __restrict__ ba,
    const float* __restrict__ W1, const float* __restrict__ b1,
    const float* __restrict__ W2, const float* __restrict__ b2,
    const float* __restrict__ W3, const float* __restrict__ b3,
    const float* __restrict__ W4, const float* __restrict__ b4,
    float* __restrict__ outp)
{
    const int b = blockIdx.x, tid = threadIdx.x;
    __shared__ float sc[TT];
    __shared__ float red[256];
    __shared__ float wash[64];
    __shared__ float att[64];
    __shared__ float h1s[128];
    __shared__ float h2s[64];
    __shared__ float h3s[32];

    if (tid < 64) wash[tid] = Wa[tid];
    __syncthreads();

    const float* o2b = g_aux + (size_t)b * TT * 64;

    // scores + local max
    float lmax = -1e30f;
    for (int t = tid; t < TT; t += 256) {
        const float4* rowp = (const float4*)(o2b + (size_t)t * 64);
        float s = 0.f;
#pragma unroll
        for (int i = 0; i < 16; i++) {
            float4 v = rowp[i];
            s += v.x * wash[4 * i] + v.y * wash[4 * i + 1]
               + v.z * wash[4 * i + 2] + v.w * wash[4 * i + 3];
        }
        s += ba[0];
        sc[t] = s;
        lmax = fmaxf(lmax, s);
    }
    red[tid] = lmax; __syncthreads();
    for (int off = 128; off > 0; off >>= 1) {
        if (tid < off) red[tid] = fmaxf(red[tid], red[tid + off]);
        __syncthreads();
    }
    const float m = red[0];
    __syncthreads();

    // exp + sum
    float lsum = 0.f;
    for (int t = tid; t < TT; t += 256) {
        float e = __expf(sc[t] - m);
        sc[t] = e;
        lsum += e;
    }
    red[tid] = lsum; __syncthreads();
    for (int off = 128; off > 0; off >>= 1) {
        if (tid < off) red[tid] += red[tid + off];
        __syncthreads();
    }
    const float inv = __fdividef(1.0f, red[0]);
    __syncthreads();

    // attended[j] = sum_t sc[t] * o2[t][j] * inv
    {
        const int j = tid & 63, ch = tid >> 6;
        const float* base = o2b + j;
        float c0 = 0.f, c1 = 0.f, c2 = 0.f, c3 = 0.f;
        const int t0 = ch * 1024;
        for (int t = t0; t < t0 + 1024; t += 4) {
            c0 += sc[t + 0] * base[(size_t)(t + 0) * 64];
            c1 += sc[t + 1] * base[(size_t)(t + 1) * 64];
            c2 += sc[t + 2] * base[(size_t)(t + 2) * 64];
            c3 += sc[t + 3] * base[(size_t)(t + 3) * 64];
        }
        red[tid] = (c0 + c1) + (c2 + c3);
    }
    __syncthreads();
    if (tid < 64)
        att[tid] = (red[tid] + red[tid + 64] + red[tid + 128] + red[tid + 192]) * inv;
    __syncthreads();

    // MLP head
    if (tid < 128) {
        float s = b1[tid];
#pragma unroll
        for (int k = 0; k < 64; k++) s += att[k] * W1[k * 128 + tid];
        h1s[tid] = fmaxf(s, 0.f);
    }
    __syncthreads();
    if (tid < 64) {
        float s = b2[tid];
#pragma unroll
        for (int k = 0; k < 128; k++) s += h1s[k] * W2[k * 64 + tid];
        h2s[tid] = fmaxf(s, 0.f);
    }
    __syncthreads();
    if (tid < 32) {
        float s = b3[tid];
#pragma unroll
        for (int k = 0; k < 64; k++) s += h2s[k] * W3[k * 32 + tid];
        h3s[tid] = fmaxf(s, 0.f);
    }
    __syncthreads();
    if (tid < 2) {
        float s = b4[tid];
#pragma unroll
        for (int k = 0; k < 32; k++) s += h3s[k] * W4[k * 2 + tid];
        outp[b * 2 + tid] = s;
    }
}

// ============================================================================
extern "C" void kernel_launch(void* const* d_in, const int* in_sizes, int n_in,
                              void* d_out, int out_size)
{
    const float* x    = (const float*)d_in[0];
    const float* Wi1  = (const float*)d_in[1];
    const float* bi1  = (const float*)d_in[2];
    const float* Whr1 = (const float*)d_in[3];
    const float* Whz1 = (const float*)d_in[4];
    const float* Whn1 = (const float*)d_in[5];
    const float* bhn1 = (const float*)d_in[6];
    const float* Wi2  = (const float*)d_in[7];
    const float* bi2  = (const float*)d_in[8];
    const float* Whr2 = (const float*)d_in[9];
    const float* Whz2 = (const float*)d_in[10];
    const float* Whn2 = (const float*)d_in[11];
    const float* bhn2 = (const float*)d_in[12];
    const float* Wp   = (const float*)d_in[13];
    const float* bp   = (const float*)d_in[14];
    const float* Wa   = (const float*)d_in[15];
    const float* ba   = (const float*)d_in[16];
    const float* W1   = (const float*)d_in[17];
    const float* b1   = (const float*)d_in[18];
    const float* W2   = (const float*)d_in[19];
    const float* b2   = (const float*)d_in[20];
    const float* W3   = (const float*)d_in[21];
    const float* b3   = (const float*)d_in[22];
    const float* W4   = (const float*)d_in[23];
    const float* b4   = (const float*)d_in[24];
    float* outp = (float*)d_out;

    // 1. xi1 = x@Wi1+bi1 -> g_xi ; xp = x@Wp+bp -> g_aux
    proj1_kernel<<<592, 256>>>(x, Wi1, bi1, Wp, bp);
    // 2. GRU layer 1 -> g_o1 = gru(x) + 0.5*xp
    gru_kernel<<<256, 128>>>(Whr1, Whz1, Whn1, bhn1, 0);
    // 3. xi2 = o1adj@Wi2+bi2 -> g_xi (reuse)
    proj2_kernel<<<296, 192>>>(Wi2, bi2);
    // 4. GRU layer 2 -> g_aux = gru(o1adj) + 0.5*o1adj  (= o2)
    gru_kernel<<<256, 128>>>(Whr2, Whz2, Whn2, bhn2, 1);
    // 5. attention softmax + MLP head -> out (B,2)
    att_mlp_kernel<<<BB, 256>>>(Wa, ba, W1, b1, W2, b2, W3, b3, W4, b4, outp);
}

// round 10
// speedup vs baseline: 1.8328x; 1.2716x over previous
#include <cuda_runtime.h>
#include <cuda_bf16.h>
#include <cstdint>

// Problem constants (fixed by the reference)
#define BB 256
#define TT 4096
#define FF 16
#define HH 64
#define NROWS (256*4096)   // 1048576 rows of (b,t)

// -------------------- scratch (device globals; no allocs allowed) -----------
__device__ float g_xi [(size_t)NROWS * 192];  // xi1, then reused as xi2 (805 MB)
__device__ float g_aux[(size_t)NROWS * 64];   // xp, then reused as o2   (268 MB)
__device__ float g_o1 [(size_t)NROWS * 64];   // o1adj                   (268 MB)

// -------------------- packed f32x2 helpers ----------------------------------
__device__ __forceinline__ unsigned long long pk2(float lo, float hi) {
    unsigned long long d;
    asm("mov.b64 %0, {%1, %2};" : "=l"(d) : "f"(lo), "f"(hi));
    return d;
}
__device__ __forceinline__ void unpk2(unsigned long long v, float& lo, float& hi) {
    asm("mov.b64 {%0, %1}, %2;" : "=f"(lo), "=f"(hi) : "l"(v));
}
__device__ __forceinline__ unsigned long long ffma2(unsigned long long a,
                                                    unsigned long long b,
                                                    unsigned long long c) {
    unsigned long long d;
    asm("fma.rn.f32x2 %0, %1, %2, %3;" : "=l"(d) : "l"(a), "l"(b), "l"(c));
    return d;
}
__device__ __forceinline__ unsigned long long fadd2(unsigned long long a,
                                                    unsigned long long b) {
    unsigned long long d;
    asm("add.rn.f32x2 %0, %1, %2;" : "=l"(d) : "l"(a), "l"(b));
    return d;
}

// HW tanh (MUFU.TANH): ~6e-4 max abs error.
__device__ __forceinline__ float tanh_mufu(float x) {
    float y;
    asm("tanh.approx.f32 %0, %1;" : "=f"(y) : "f"(x));
    return y;
}

__device__ __forceinline__ uint32_t f2tf32(float f) {
    uint32_t u;
    asm("cvt.rna.tf32.f32 %0, %1;" : "=r"(u) : "f"(f));
    return u;
}

// ============================================================================
// proj1: for each (b,t) row: xi1 = x@Wi1 + bi1 (192), xp = x@Wp + bp (64)
// ============================================================================
__global__ __launch_bounds__(256) void proj1_kernel(
    const float* __restrict__ X,
    const float* __restrict__ Wi1, const float* __restrict__ bi1,
    const float* __restrict__ Wp,  const float* __restrict__ bp)
{
    __shared__ __align__(16) unsigned long long xdup[8][16];  // 8 rows x 16 dup-pairs

    const int tid = threadIdx.x;
    const int j2  = tid & 127;   // output pair index
    const int rr  = tid >> 7;    // 0..1

    unsigned long long wp_[16];
    unsigned long long bias;
    if (j2 < 96) {               // xi columns 0..191
        const int c0 = 2 * j2;
#pragma unroll
        for (int k = 0; k < 16; k++)
            wp_[k] = pk2(Wi1[k * 192 + c0], Wi1[k * 192 + c0 + 1]);
        bias = pk2(bi1[c0], bi1[c0 + 1]);
    } else {                     // xp columns 0..63
        const int c0 = 2 * j2 - 192;
#pragma unroll
        for (int k = 0; k < 16; k++)
            wp_[k] = pk2(Wp[k * 64 + c0], Wp[k * 64 + c0 + 1]);
        bias = pk2(bp[c0], bp[c0 + 1]);
    }

    for (size_t r0 = (size_t)blockIdx.x * 8; r0 < (size_t)NROWS;
         r0 += (size_t)gridDim.x * 8) {
        if (tid < 32) {
            const float4* xs = (const float4*)(X + r0 * 16);
            float4 v = xs[tid];
            int row = tid >> 2, c4 = (tid & 3) * 4;
            xdup[row][c4 + 0] = pk2(v.x, v.x);
            xdup[row][c4 + 1] = pk2(v.y, v.y);
            xdup[row][c4 + 2] = pk2(v.z, v.z);
            xdup[row][c4 + 3] = pk2(v.w, v.w);
        }
        __syncthreads();
#pragma unroll
        for (int q = 0; q < 4; q++) {
            const int rw = rr * 4 + q;
            const ulonglong2* xr = (const ulonglong2*)&xdup[rw][0];
            unsigned long long acc = bias;
#pragma unroll
            for (int i = 0; i < 8; i++) {
                ulonglong2 u = xr[i];
                acc = ffma2(u.x, wp_[2 * i], acc);
                acc = ffma2(u.y, wp_[2 * i + 1], acc);
            }
            const size_t row = r0 + rw;
            if (j2 < 96)
                *(unsigned long long*)(g_xi + row * 192 + 2 * j2) = acc;
            else
                *(unsigned long long*)(g_aux + row * 64 + (2 * j2 - 192)) = acc;
        }
        __syncthreads();
    }
}

// ============================================================================
// proj2 via tf32 tensor-core mma: xi2 = o1adj @ Wi2 + bi2
// CTA = 128 threads (4 warps). Each CTA owns one 96-col half (blockIdx.x&1)
// and grid-strides over 64-row tiles. B-half (64x96 tf32) loaded to shared
// once per CTA; A tile (64x64 tf32) staged per iter. Padded strides give
// conflict-free fragment LDS: A stride 68 (bank = 4r+c), B stride 104
// (bank = 8k+c). Warp w computes rows [16w,16w+16) x 96 cols = 12 n8-tiles,
// 48 accum regs. K=64 -> 8 mma k-steps.
// ============================================================================
__global__ __launch_bounds__(128) void proj2_mma_kernel(
    const float* __restrict__ Wi2, const float* __restrict__ bi2)
{
    __shared__ uint32_t As[64][68];    // 17408 B
    __shared__ uint32_t Bs[64][104];   // 26624 B

    const int tid  = threadIdx.x;
    const int warp = tid >> 5, lane = tid & 31;
    const int g    = lane >> 2, tig = lane & 3;
    const int half = blockIdx.x & 1;
    const int cb   = 96 * half;

    // Load B half: 64 rows x 96 cols, cvt to tf32
    for (int f = tid; f < 64 * 24; f += 128) {
        int row = f / 24, c4 = (f % 24) * 4;
        float4 v = *(const float4*)(Wi2 + row * 192 + cb + c4);
        uint4 t;
        t.x = f2tf32(v.x); t.y = f2tf32(v.y);
        t.z = f2tf32(v.z); t.w = f2tf32(v.w);
        *(uint4*)&Bs[row][c4] = t;
    }

    const size_t rstep = (size_t)(gridDim.x >> 1) * 64;
    for (size_t r0 = (size_t)(blockIdx.x >> 1) * 64; r0 < (size_t)NROWS;
         r0 += rstep) {
        __syncthreads();   // B ready (iter 0) / prev mma reads of As done
        // Stage A tile 64x64 -> tf32 shared
        for (int f = tid; f < 64 * 16; f += 128) {
            int row = f >> 4, c4 = (f & 15) * 4;
            float4 v = *(const float4*)(g_o1 + (r0 + row) * 64 + c4);
            uint4 t;
            t.x = f2tf32(v.x); t.y = f2tf32(v.y);
            t.z = f2tf32(v.z); t.w = f2tf32(v.w);
            *(uint4*)&As[row][c4] = t;
        }
        __syncthreads();

        float acc[12][4];
#pragma unroll
        for (int nt = 0; nt < 12; nt++)
            acc[nt][0] = acc[nt][1] = acc[nt][2] = acc[nt][3] = 0.f;

        const int rw = warp * 16;
#pragma unroll
        for (int ks = 0; ks < 8; ks++) {
            const int k0 = ks * 8;
            uint32_t a0 = As[rw + g    ][k0 + tig];
            uint32_t a1 = As[rw + g + 8][k0 + tig];
            uint32_t a2 = As[rw + g    ][k0 + tig + 4];
            uint32_t a3 = As[rw + g + 8][k0 + tig + 4];
#pragma unroll
            for (int nt = 0; nt < 12; nt++) {
                uint32_t b0 = Bs[k0 + tig    ][nt * 8 + g];
                uint32_t b1 = Bs[k0 + tig + 4][nt * 8 + g];
                asm("mma.sync.aligned.m16n8k8.row.col.f32.tf32.tf32.f32 "
                    "{%0,%1,%2,%3}, {%4,%5,%6,%7}, {%8,%9}, {%0,%1,%2,%3};"
                    : "+f"(acc[nt][0]), "+f"(acc[nt][1]),
                      "+f"(acc[nt][2]), "+f"(acc[nt][3])
                    : "r"(a0), "r"(a1), "r"(a2), "r"(a3), "r"(b0), "r"(b1));
            }
        }

        // Epilogue: + bias, store fp32
#pragma unroll
        for (int nt = 0; nt < 12; nt++) {
            const int c0 = cb + nt * 8 + 2 * tig;
            const float2 bias = *(const float2*)(bi2 + c0);
            const size_t row = r0 + rw + g;
            float2 o0 = make_float2(acc[nt][0] + bias.x, acc[nt][1] + bias.y);
            float2 o1v = make_float2(acc[nt][2] + bias.x, acc[nt][3] + bias.y);
            *(float2*)(g_xi + row * 192 + c0) = o0;
            *(float2*)(g_xi + (row + 8) * 192 + c0) = o1v;
        }
    }
}

// ============================================================================
// GRU recurrence — R7 micro-optimized.
// One CTA per batch row, 128 threads = 64 columns x 2 k-halves.
// Changes vs R5:
//  - prefetch LDGs issued AFTER the dot FFMAs (critical LDS of h no longer
//    queues behind 3-4 LDG wavefronts in the L1tex FIFO at barrier release;
//    LDGs fill the gate-tail latency shadow instead)
//  - n-gate tanh via MUFU.TANH (replaces ~45-cyc __expf/__fdividef chain)
//  - r/z weights pre-scaled by 0.5 so sigma(x)=0.5*tanh(0.5x)+0.5 needs one
//    FMA on the critical path instead of ADD+MUL
// ============================================================================
__global__ __launch_bounds__(128, 2) void gru_kernel(
    const float* __restrict__ Whr, const float* __restrict__ Whz,
    const float* __restrict__ Whn, const float* __restrict__ bhn,
    int layer2)
{
    const int tid = threadIdx.x;
    const int j   = tid >> 1;     // 0..63 output column
    const int s   = tid & 1;      // k-half
    const int b   = blockIdx.x;
    const int k0  = 32 * s;

    const float* aux = layer2 ? g_o1 : g_aux;
    float*       out = layer2 ? g_aux : g_o1;

    __shared__ __align__(16) float hbuf[2][72];  // halves at [0,32) and [36,68)

    unsigned long long wr_[16], wz_[16], wn_[16];
#pragma unroll
    for (int i = 0; i < 16; i++) {
        // r/z kernels pre-scaled by 0.5 (sigmoid-via-tanh folding)
        wr_[i] = pk2(0.5f * Whr[(k0 + 2 * i) * 64 + j],
                     0.5f * Whr[(k0 + 2 * i + 1) * 64 + j]);
        wz_[i] = pk2(0.5f * Whz[(k0 + 2 * i) * 64 + j],
                     0.5f * Whz[(k0 + 2 * i + 1) * 64 + j]);
        wn_[i] = pk2(Whn[(k0 + 2 * i) * 64 + j],
                     Whn[(k0 + 2 * i + 1) * 64 + j]);
    }
    const float bn   = bhn[j];
    const int   jpad = j + ((j >> 5) << 2);   // j<32 -> j ; j>=32 -> j+4

    if (tid < 72) hbuf[0][tid] = 0.0f;        // h0 = 0 (covers both halves+pad)

    const float* pr = g_xi + (size_t)b * TT * 192 + j;
    const float* pz = pr + 64;
    const float* pn = pr + 128;
    const float* pa = aux + (size_t)b * TT * 64 + j;
    float*       op = out + (size_t)b * TT * 64 + j;

    // 4-deep register prefetch queues (slot u refilled with step tb+u+4)
    float qr[4], qz[4], qn[4], qa[4] = {0.f, 0.f, 0.f, 0.f};
#pragma unroll
    for (int u = 0; u < 4; u++) {
        qr[u] = __ldg(pr + u * 192);
        qz[u] = __ldg(pz + u * 192);
        qn[u] = __ldg(pn + u * 192);
        if (s) qa[u] = __ldg(pa + u * 64);
    }
    pr += 4 * 192; pz += 4 * 192; pn += 4 * 192; pa += 4 * 64;

    float hprev = 0.0f;
    __syncthreads();

    int buf = 0;
    for (int tb = 0; tb < TT; tb += 4) {
        const bool pf = (tb + 4) < TT;
#pragma unroll
        for (int u = 0; u < 4; u++) {
            const float ir = qr[u], iz = qz[u], inn = qn[u], av = qa[u];

            // ---- critical LDS + partial dots FIRST (no LDGs ahead of them)
            const ulonglong2* hp = (const ulonglong2*)&hbuf[buf][36 * s];
            unsigned long long r0 = 0ull, r1 = 0ull, z0 = 0ull, z1 = 0ull,
                               n0 = 0ull, n1 = 0ull;
#pragma unroll
            for (int i = 0; i < 8; i++) {
                ulonglong2 h2 = hp[i];
                r0 = ffma2(h2.x, wr_[2 * i],     r0);
                r1 = ffma2(h2.y, wr_[2 * i + 1], r1);
                z0 = ffma2(h2.x, wz_[2 * i],     z0);
                z1 = ffma2(h2.y, wz_[2 * i + 1], z1);
                n0 = ffma2(h2.x, wn_[2 * i],     n0);
                n1 = ffma2(h2.y, wn_[2 * i + 1], n1);
            }

            // ---- prefetch t+4 now (fills the gate-tail latency shadow)
            if (pf) {
                qr[u] = __ldg(pr); qz[u] = __ldg(pz); qn[u] = __ldg(pn);
                if (s) qa[u] = __ldg(pa);
            }
            pr += 192; pz += 192; pn += 192; pa += 64;

            float lo, hi;
            r0 = fadd2(r0, r1); unpk2(r0, lo, hi); float dr = lo + hi; // = 0.5*dot_r
            z0 = fadd2(z0, z1); unpk2(z0, lo, hi); float dz = lo + hi; // = 0.5*dot_z
            n0 = fadd2(n0, n1); unpk2(n0, lo, hi); float dn = lo + hi;
            dr += __shfl_xor_sync(0xffffffffu, dr, 1);
            dz += __shfl_xor_sync(0xffffffffu, dz, 1);
            dn += __shfl_xor_sync(0xffffffffu, dn, 1);

            // sigma(x) = 0.5*tanh(0.5x)+0.5 ; 0.5*dot already folded in
            const float rg = fmaf(0.5f, tanh_mufu(fmaf(0.5f, ir, dr)), 0.5f);
            const float zg = fmaf(0.5f, tanh_mufu(fmaf(0.5f, iz, dz)), 0.5f);
            const float n  = tanh_mufu(fmaf(rg, dn + bn, inn));
            const float hn = n + zg * (hprev - n);
            hprev = hn;
            if (s) *op = hn + 0.5f * av;          // s=1: write output
            else   hbuf[buf ^ 1][jpad] = hn;      // s=0: publish h for t+1
            op += 64;
            __syncthreads();                      // single barrier per step
            buf ^= 1;
        }
    }
}

// ============================================================================
// Attention (softmax over T) + MLP head. One CTA per batch element.
// ============================================================================
__global__ __launch_bounds__(256) void att_mlp_kernel(
    const float* __restrict__ Wa, const float* __restrict__ ba,
    const float* __restrict__ W1, const float* __restrict__ b1,
    const float* __restrict__ W2, const float* __restrict__ b2,
    const float* __restrict__ W3, const float* __restrict__ b3,
    const float* __restrict__ W4, const float* __restrict__ b4,
    float* __restrict__ outp)
{
    const int b = blockIdx.x, tid = threadIdx.x;
    __shared__ float sc[TT];
    __shared__ float red[256];
    __shared__ float wash[64];
    __shared__ float att[64];
    __shared__ float h1s[128];
    __shared__ float h2s[64];
    __shared__ float h3s[32];

    if (tid < 64) wash[tid] = Wa[tid];
    __syncthreads();

    const float* o2b = g_aux + (size_t)b * TT * 64;

    // scores + local max
    float lmax = -1e30f;
    for (int t = tid; t < TT; t += 256) {
        const float4* rowp = (const float4*)(o2b + (size_t)t * 64);
        float s = 0.f;
#pragma unroll
        for (int i = 0; i < 16; i++) {
            float4 v = rowp[i];
            s += v.x * wash[4 * i] + v.y * wash[4 * i + 1]
               + v.z * wash[4 * i + 2] + v.w * wash[4 * i + 3];
        }
        s += ba[0];
        sc[t] = s;
        lmax = fmaxf(lmax, s);
    }
    red[tid] = lmax; __syncthreads();
    for (int off = 128; off > 0; off >>= 1) {
        if (tid < off) red[tid] = fmaxf(red[tid], red[tid + off]);
        __syncthreads();
    }
    const float m = red[0];
    __syncthreads();

    // exp + sum
    float lsum = 0.f;
    for (int t = tid; t < TT; t += 256) {
        float e = __expf(sc[t] - m);
        sc[t] = e;
        lsum += e;
    }
    red[tid] = lsum; __syncthreads();
    for (int off = 128; off > 0; off >>= 1) {
        if (tid < off) red[tid] += red[tid + off];
        __syncthreads();
    }
    const float inv = __fdividef(1.0f, red[0]);
    __syncthreads();

    // attended[j] = sum_t sc[t] * o2[t][j] * inv
    {
        const int j = tid & 63, ch = tid >> 6;
        const float* base = o2b + j;
        float c0 = 0.f, c1 = 0.f, c2 = 0.f, c3 = 0.f;
        const int t0 = ch * 1024;
        for (int t = t0; t < t0 + 1024; t += 4) {
            c0 += sc[t + 0] * base[(size_t)(t + 0) * 64];
            c1 += sc[t + 1] * base[(size_t)(t + 1) * 64];
            c2 += sc[t + 2] * base[(size_t)(t + 2) * 64];
            c3 += sc[t + 3] * base[(size_t)(t + 3) * 64];
        }
        red[tid] = (c0 + c1) + (c2 + c3);
    }
    __syncthreads();
    if (tid < 64)
        att[tid] = (red[tid] + red[tid + 64] + red[tid + 128] + red[tid + 192]) * inv;
    __syncthreads();

    // MLP head
    if (tid < 128) {
        float s = b1[tid];
#pragma unroll
        for (int k = 0; k < 64; k++) s += att[k] * W1[k * 128 + tid];
        h1s[tid] = fmaxf(s, 0.f);
    }
    __syncthreads();
    if (tid < 64) {
        float s = b2[tid];
#pragma unroll
        for (int k = 0; k < 128; k++) s += h1s[k] * W2[k * 64 + tid];
        h2s[tid] = fmaxf(s, 0.f);
    }
    __syncthreads();
    if (tid < 32) {
        float s = b3[tid];
#pragma unroll
        for (int k = 0; k < 64; k++) s += h2s[k] * W3[k * 32 + tid];
        h3s[tid] = fmaxf(s, 0.f);
    }
    __syncthreads();
    if (tid < 2) {
        float s = b4[tid];
#pragma unroll
        for (int k = 0; k < 32; k++) s += h3s[k] * W4[k * 2 + tid];
        outp[b * 2 + tid] = s;
    }
}

// ============================================================================
extern "C" void kernel_launch(void* const* d_in, const int* in_sizes, int n_in,
                              void* d_out, int out_size)
{
    const float* x    = (const float*)d_in[0];
    const float* Wi1  = (const float*)d_in[1];
    const float* bi1  = (const float*)d_in[2];
    const float* Whr1 = (const float*)d_in[3];
    const float* Whz1 = (const float*)d_in[4];
    const float* Whn1 = (const float*)d_in[5];
    const float* bhn1 = (const float*)d_in[6];
    const float* Wi2  = (const float*)d_in[7];
    const float* bi2  = (const float*)d_in[8];
    const float* Whr2 = (const float*)d_in[9];
    const float* Whz2 = (const float*)d_in[10];
    const float* Whn2 = (const float*)d_in[11];
    const float* bhn2 = (const float*)d_in[12];
    const float* Wp   = (const float*)d_in[13];
    const float* bp   = (const float*)d_in[14];
    const float* Wa   = (const float*)d_in[15];
    const float* ba   = (const float*)d_in[16];
    const float* W1   = (const float*)d_in[17];
    const float* b1   = (const float*)d_in[18];
    const float* W2   = (const float*)d_in[19];
    const float* b2   = (const float*)d_in[20];
    const float* W3   = (const float*)d_in[21];
    const float* b3   = (const float*)d_in[22];
    const float* W4   = (const float*)d_in[23];
    const float* b4   = (const float*)d_in[24];
    float* outp = (float*)d_out;

    // 1. xi1 = x@Wi1+bi1 -> g_xi ; xp = x@Wp+bp -> g_aux
    proj1_kernel<<<592, 256>>>(x, Wi1, bi1, Wp, bp);
    // 2. GRU layer 1 -> g_o1 = gru(x) + 0.5*xp
    gru_kernel<<<256, 128>>>(Whr1, Whz1, Whn1, bhn1, 0);
    // 3. xi2 = o1adj@Wi2+bi2 -> g_xi (reuse)  [tf32 tensor cores]
    proj2_mma_kernel<<<740, 128>>>(Wi2, bi2);
    // 4. GRU layer 2 -> g_aux = gru(o1adj) + 0.5*o1adj  (= o2)
    gru_kernel<<<256, 128>>>(Whr2, Whz2, Whn2, bhn2, 1);
    // 5. attention softmax + MLP head -> out (B,2)
    att_mlp_kernel<<<BB, 256>>>(Wa, ba, W1, b1, W2, b2, W3, b3, W4, b4, outp);
}